// round 8
// baseline (speedup 1.0000x reference)
#include <cuda_runtime.h>
#include <cuda_fp16.h>
#include <cstdint>

#define NB 8
#define NL 256
#define NF 6272
#define NU 32
#define KSPLIT 14

// Scratch (no cudaMalloc allowed)
__device__ float g_p[NB*NL*NU];                      // reduced projections
__device__ float g_pp[KSPLIT*NB*NL*NU];              // projection partials (deterministic)
__device__ __half g_af[NB*NL*NL];                    // a (softmax) fp16 [b][q][k]
__device__ __half g_xh[(size_t)NB*NL*NF];            // inputs fp16 [b][k][f] (written by k_proj)

// ---------------------------------------------------------------------------
// helpers
// ---------------------------------------------------------------------------
__device__ __forceinline__ uint32_t s2u(const void* p){
    uint32_t a;
    asm("{ .reg .u64 t; cvta.to.shared.u64 t, %1; cvt.u32.u64 %0, t; }" : "=r"(a) : "l"(p));
    return a;
}
__device__ __forceinline__ float tanh_approx(float x){
    float y; asm("tanh.approx.f32 %0, %1;" : "=f"(y) : "f"(x)); return y;
}
__device__ __forceinline__ void ldsm4(uint32_t r[4], uint32_t a){
    asm volatile("ldmatrix.sync.aligned.m8n8.x4.shared.b16 {%0,%1,%2,%3}, [%4];"
                 : "=r"(r[0]), "=r"(r[1]), "=r"(r[2]), "=r"(r[3]) : "r"(a));
}
__device__ __forceinline__ void ldsm4t(uint32_t r[4], uint32_t a){
    asm volatile("ldmatrix.sync.aligned.m8n8.x4.trans.shared.b16 {%0,%1,%2,%3}, [%4];"
                 : "=r"(r[0]), "=r"(r[1]), "=r"(r[2]), "=r"(r[3]) : "r"(a));
}
__device__ __forceinline__ void mma_f16(float c[4], const uint32_t a[4], uint32_t b0, uint32_t b1){
    asm volatile(
        "mma.sync.aligned.m16n8k16.row.col.f32.f16.f16.f32 "
        "{%0,%1,%2,%3}, {%4,%5,%6,%7}, {%8,%9}, {%0,%1,%2,%3};"
        : "+f"(c[0]), "+f"(c[1]), "+f"(c[2]), "+f"(c[3])
        : "r"(a[0]), "r"(a[1]), "r"(a[2]), "r"(a[3]), "r"(b0), "r"(b1));
}
__device__ __forceinline__ uint2 cvt4h(float4 v){
    __half h[4];
    h[0] = __float2half(v.x); h[1] = __float2half(v.y);
    h[2] = __float2half(v.z); h[3] = __float2half(v.w);
    return *(uint2*)h;
}
__device__ __forceinline__ void cp16(uint32_t dst, const void* src){
    asm volatile("cp.async.cg.shared.global [%0], [%1], 16;" :: "r"(dst), "l"(src));
}
__device__ __forceinline__ void cp_commit(){ asm volatile("cp.async.commit_group;"); }
__device__ __forceinline__ void cp_wait1(){ asm volatile("cp.async.wait_group 1;"); }

// ---------------------------------------------------------------------------
// K_proj: p_partial[by] = x[rows, fchunk] @ Wt[fchunk, 32]  (fp16 HMMA, 1 term)
// Also writes g_xh (inputs as fp16) as a byproduct.
// grid (16, 14), 256 threads.
// ---------------------------------------------------------------------------
__global__ __launch_bounds__(256) void k_proj(const float* __restrict__ inp,
                                              const float* __restrict__ Wt){
    __shared__ __half Ah[128][40];
    __shared__ __half Bh[32][40];
    const int t = threadIdx.x, wid = t >> 5, l = t & 31;
    const int lr = l & 15, lc = (l >> 4) << 3;
    const int row0 = blockIdx.x * 128;
    const int fb0  = blockIdx.y * 448;

    const int arR[4] = { (t+0)>>3, (t+256)>>3, (t+512)>>3, (t+768)>>3 };
    const int arC    = (t & 7)*4;
    const int wrR    = t >> 3, wrC = (t & 7)*4;

    float acc[4][4];
    #pragma unroll
    for (int i = 0; i < 4; i++)
        #pragma unroll
        for (int j = 0; j < 4; j++) acc[i][j] = 0.f;

    const uint32_t a_ah = s2u(Ah), a_bh = s2u(Bh);

    float4 xv[4], wv;
    #pragma unroll
    for (int i = 0; i < 4; i++)
        xv[i] = *(const float4*)(inp + (size_t)(row0 + arR[i])*NF + fb0 + arC);
    wv = *(const float4*)(Wt + (size_t)(fb0 + wrR)*NU + wrC);

    for (int s = 0; s < 14; s++){
        const int fb = fb0 + s*32;
        #pragma unroll
        for (int i = 0; i < 4; i++){
            uint2 h = cvt4h(xv[i]);
            *(uint2*)&Ah[arR[i]][arC] = h;
            *(uint2*)&g_xh[(size_t)(row0 + arR[i])*NF + fb + arC] = h;
        }
        *(uint2*)&Bh[wrR][wrC] = cvt4h(wv);
        __syncthreads();

        if (s < 13){
            const int fbn = fb0 + (s+1)*32;
            #pragma unroll
            for (int i = 0; i < 4; i++)
                xv[i] = *(const float4*)(inp + (size_t)(row0 + arR[i])*NF + fbn + arC);
            wv = *(const float4*)(Wt + (size_t)(fbn + wrR)*NU + wrC);
        }

        #pragma unroll
        for (int ks = 0; ks < 32; ks += 16){
            uint32_t fa[4];
            ldsm4(fa, a_ah + ((wid*16 + lr)*40 + ks + lc)*2);
            uint32_t fb4[8];
            ldsm4t(fb4 + 0, a_bh + ((ks + lr)*40 + 0  + lc)*2);
            ldsm4t(fb4 + 4, a_bh + ((ks + lr)*40 + 16 + lc)*2);
            #pragma unroll
            for (int ng = 0; ng < 4; ng++)
                mma_f16(acc[ng], fa, fb4[ng*2], fb4[ng*2+1]);
        }
        __syncthreads();
    }
    float* pp = g_pp + (size_t)blockIdx.y*NB*NL*NU;
    const int r0 = row0 + wid*16 + (l >> 2);
    const int c0 = (l & 3)*2;
    #pragma unroll
    for (int ng = 0; ng < 4; ng++){
        *(float2*)&pp[(size_t)r0*NU + ng*8 + c0]     = make_float2(acc[ng][0], acc[ng][1]);
        *(float2*)&pp[(size_t)(r0+8)*NU + ng*8 + c0] = make_float2(acc[ng][2], acc[ng][3]);
    }
}

// ---------------------------------------------------------------------------
// K_pred: reduce partials -> g_p
// ---------------------------------------------------------------------------
__global__ __launch_bounds__(256) void k_pred(){
    int i = blockIdx.x*256 + threadIdx.x;
    float s = 0.f;
    #pragma unroll
    for (int j = 0; j < KSPLIT; j++) s += g_pp[(size_t)j*NB*NL*NU + i];
    g_p[i] = s;
}

// ---------------------------------------------------------------------------
// K_attn: block handles (b, 8 queries). grid (32, 8), 256 threads (t = k).
// ---------------------------------------------------------------------------
__global__ __launch_bounds__(256) void k_attn(const float* __restrict__ bh,
                                              const float* __restrict__ Wa,
                                              const float* __restrict__ ba){
    __shared__ float ps[NL][33];
    __shared__ float pqb[8][32];
    __shared__ float was[32];
    __shared__ float red[8][8];
    __shared__ float inv[8];

    const int t = threadIdx.x;
    const int b = blockIdx.y;
    const int q0 = blockIdx.x * 8;
    const float* pb = g_p + b*NL*NU;
    const float ba0 = ba[0];

    #pragma unroll
    for (int i = 0; i < 32; i++){
        int idx = t + i*256;
        ps[idx >> 5][idx & 31] = pb[idx];
    }
    if (t < 32) was[t] = Wa[t];
    {
        int j = t >> 5, u = t & 31;
        pqb[j][u] = pb[(q0 + j)*NU + u] + bh[u];
    }
    __syncthreads();

    float e[8];
    #pragma unroll
    for (int j = 0; j < 8; j++){
        float acc = 0.f;
        #pragma unroll
        for (int u = 0; u < 32; u++)
            acc = fmaf(was[u], tanh_approx(pqb[j][u] + ps[t][u]), acc);
        float alpha = acc + ba0;
        float sg = 1.f / (1.f + __expf(-alpha));
        e[j] = __expf(sg);
    }

    #pragma unroll
    for (int j = 0; j < 8; j++){
        float w = e[j];
        #pragma unroll
        for (int o = 16; o > 0; o >>= 1) w += __shfl_xor_sync(0xffffffffu, w, o);
        if ((t & 31) == 0) red[t >> 5][j] = w;
    }
    __syncthreads();
    if (t < 8){
        float tot = 0.f;
        #pragma unroll
        for (int w = 0; w < 8; w++) tot += red[w][t];
        inv[t] = 1.f / tot;
    }
    __syncthreads();

    #pragma unroll
    for (int j = 0; j < 8; j++)
        g_af[(size_t)b*NL*NL + (size_t)(q0 + j)*NL + t] = __float2half(e[j] * inv[j]);
}

// ---------------------------------------------------------------------------
// K_out: out[b,q,f] = sum_k a[b,q,k]*x[b,k,f]   (single fp16 HMMA term)
// BM=128, BN=128, BK=32; 4 warps 2(M)x2(N), warp tile 64x64.
// Both operands fp16 in gmem -> pure cp.async.cg staging, 3-stage pipeline.
// grid (49, 2, 8), 128 threads, 2 CTA/SM.
// ---------------------------------------------------------------------------
// stage layout (bytes): Af 128*40*2 = 10240 | Bf 32*136*2 = 8704  -> 18944
#define STG    18944
#define OFF_B  10240
#define NSTAGE 3
#define K3_SMEM (NSTAGE*STG)

__global__ __launch_bounds__(128, 2) void k_out(float* __restrict__ out){
    extern __shared__ char sm[];
    const uint32_t smb = s2u(sm);
    const int t = threadIdx.x, wid = t >> 5, l = t & 31;
    const int lr = l & 15, lc = (l >> 4) << 3;
    const int b  = blockIdx.z;
    const int q0 = blockIdx.y * 128;
    const int f0 = blockIdx.x * 128;
    const int warp_m = wid >> 1, warp_n = wid & 1;   // 2 x 2

    const __half* gaf = g_af + ((size_t)b*NL + q0)*NL;
    const __half* gx  = g_xh + (size_t)b*NL*NF + f0;

    // A staging: 128 rows x 32 k fp16 = 512 x 16B -> 4 cp16/thread (128 thr)
    int aR[4];
    #pragma unroll
    for (int i = 0; i < 4; i++) aR[i] = (t + i*128) >> 2;
    const int aC = (t & 3)*8;                    // halves (16B)
    // B staging: 32 rows x 128 f fp16 = 512 x 16B -> 4 cp16/thread
    int bRr[4];
    #pragma unroll
    for (int i = 0; i < 4; i++) bRr[i] = (t + i*128) >> 4;
    const int bCc = (t & 15)*8;                  // halves (16B)

    float acc[4][8][4];
    #pragma unroll
    for (int mt = 0; mt < 4; mt++)
        #pragma unroll
        for (int ng = 0; ng < 8; ng++)
            #pragma unroll
            for (int k = 0; k < 4; k++) acc[mt][ng][k] = 0.f;

    // ---- prologue: issue stages for chunks 0 and 1
    #pragma unroll
    for (int c = 0; c < 2; c++){
        const uint32_t st = smb + c*STG;
        const int k0 = c*32;
        #pragma unroll
        for (int i = 0; i < 4; i++){
            cp16(st + (uint32_t)aR[i]*80 + aC*2,            gaf + (size_t)aR[i]*NL + k0 + aC);
            cp16(st + OFF_B + (uint32_t)bRr[i]*272 + bCc*2, gx + (size_t)(k0 + bRr[i])*NF + bCc);
        }
        cp_commit();
    }

    for (int c = 0; c < 8; c++){
        cp_wait1();            // stage c complete (<=1 group outstanding)
        __syncthreads();

        if (c + 2 < 8){
            const uint32_t st = smb + ((c+2) % NSTAGE)*STG;
            const int k0 = (c+2)*32;
            #pragma unroll
            for (int i = 0; i < 4; i++){
                cp16(st + (uint32_t)aR[i]*80 + aC*2,            gaf + (size_t)aR[i]*NL + k0 + aC);
                cp16(st + OFF_B + (uint32_t)bRr[i]*272 + bCc*2, gx + (size_t)(k0 + bRr[i])*NF + bCc);
            }
        }
        cp_commit();

        const uint32_t base = smb + (c % NSTAGE)*STG;
        #pragma unroll
        for (int ks = 0; ks < 32; ks += 16){
            uint32_t fb4[16];
            #pragma unroll
            for (int g = 0; g < 4; g++)
                ldsm4t(fb4 + g*4, base + OFF_B + ((ks + lr)*136 + warp_n*64 + g*16 + lc)*2);
            #pragma unroll
            for (int mt = 0; mt < 4; mt++){
                uint32_t fa[4];
                ldsm4(fa, base + ((warp_m*64 + mt*16 + lr)*40 + ks + lc)*2);
                #pragma unroll
                for (int ng = 0; ng < 8; ng++)
                    mma_f16(acc[mt][ng], fa, fb4[ng*2], fb4[ng*2+1]);
            }
        }
    }

    // epilogue
    const int c0 = (l & 3)*2;
    #pragma unroll
    for (int mt = 0; mt < 4; mt++){
        const int row = q0 + warp_m*64 + mt*16 + (l >> 2);
        #pragma unroll
        for (int ng = 0; ng < 8; ng++){
            const int col = f0 + warp_n*64 + ng*8 + c0;
            *(float2*)&out[((size_t)(b*NL + row))*NF + col] =
                make_float2(acc[mt][ng][0], acc[mt][ng][1]);
            *(float2*)&out[((size_t)(b*NL + row + 8))*NF + col] =
                make_float2(acc[mt][ng][2], acc[mt][ng][3]);
        }
    }
}

// ---------------------------------------------------------------------------
extern "C" void kernel_launch(void* const* d_in, const int* in_sizes, int n_in,
                              void* d_out, int out_size){
    const float* inp = (const float*)d_in[0];
    const float* Wt  = (const float*)d_in[1];
    const float* bh  = (const float*)d_in[2];
    const float* Wa  = (const float*)d_in[3];
    const float* ba  = (const float*)d_in[4];
    float* out = (float*)d_out;

    static bool attr_set = false;
    if (!attr_set){
        cudaFuncSetAttribute(k_out, cudaFuncAttributeMaxDynamicSharedMemorySize, K3_SMEM);
        attr_set = true;
    }

    k_proj<<<dim3(16, KSPLIT), 256>>>(inp, Wt);
    k_pred<<<NB*NL*NU/256, 256>>>();
    k_attn<<<dim3(NL/8, NB), 256>>>(bh, Wa, ba);
    k_out<<<dim3(NF/128, NL/128, NB), 128, K3_SMEM>>>(out);
}

// round 9
// speedup vs baseline: 1.0973x; 1.0973x over previous
#include <cuda_runtime.h>
#include <cuda_fp16.h>
#include <cstdint>

#define NB 8
#define NL 256
#define NF 6272
#define NU 32
#define KSPLIT 28

// Scratch (no cudaMalloc allowed)
__device__ float g_p[NB*NL*NU];                      // reduced projections
__device__ float g_pp[KSPLIT*NB*NL*NU];              // projection partials (deterministic)
__device__ __half g_af[NB*NL*NL];                    // a (softmax) fp16 [b][q][k]
__device__ __half g_xh[(size_t)NB*NL*NF];            // inputs fp16 [b][k][f] (written by k_proj)

// ---------------------------------------------------------------------------
// helpers
// ---------------------------------------------------------------------------
__device__ __forceinline__ uint32_t s2u(const void* p){
    uint32_t a;
    asm("{ .reg .u64 t; cvta.to.shared.u64 t, %1; cvt.u32.u64 %0, t; }" : "=r"(a) : "l"(p));
    return a;
}
__device__ __forceinline__ float tanh_approx(float x){
    float y; asm("tanh.approx.f32 %0, %1;" : "=f"(y) : "f"(x)); return y;
}
__device__ __forceinline__ void ldsm4(uint32_t r[4], uint32_t a){
    asm volatile("ldmatrix.sync.aligned.m8n8.x4.shared.b16 {%0,%1,%2,%3}, [%4];"
                 : "=r"(r[0]), "=r"(r[1]), "=r"(r[2]), "=r"(r[3]) : "r"(a));
}
__device__ __forceinline__ void ldsm4t(uint32_t r[4], uint32_t a){
    asm volatile("ldmatrix.sync.aligned.m8n8.x4.trans.shared.b16 {%0,%1,%2,%3}, [%4];"
                 : "=r"(r[0]), "=r"(r[1]), "=r"(r[2]), "=r"(r[3]) : "r"(a));
}
__device__ __forceinline__ void mma_f16(float c[4], const uint32_t a[4], uint32_t b0, uint32_t b1){
    asm volatile(
        "mma.sync.aligned.m16n8k16.row.col.f32.f16.f16.f32 "
        "{%0,%1,%2,%3}, {%4,%5,%6,%7}, {%8,%9}, {%0,%1,%2,%3};"
        : "+f"(c[0]), "+f"(c[1]), "+f"(c[2]), "+f"(c[3])
        : "r"(a[0]), "r"(a[1]), "r"(a[2]), "r"(a[3]), "r"(b0), "r"(b1));
}
__device__ __forceinline__ uint2 cvt4h(float4 v){
    __half h[4];
    h[0] = __float2half(v.x); h[1] = __float2half(v.y);
    h[2] = __float2half(v.z); h[3] = __float2half(v.w);
    return *(uint2*)h;
}
__device__ __forceinline__ void cp16(uint32_t dst, const void* src){
    asm volatile("cp.async.cg.shared.global [%0], [%1], 16;" :: "r"(dst), "l"(src));
}
__device__ __forceinline__ void cp_commit(){ asm volatile("cp.async.commit_group;"); }
__device__ __forceinline__ void cp_wait1(){ asm volatile("cp.async.wait_group 1;"); }

// ---------------------------------------------------------------------------
// K_proj: p_partial[by] = x[rows, fchunk] @ Wt[fchunk, 32]  (fp16 HMMA, 1 term)
// Also writes g_xh (inputs as fp16) as a byproduct.
// grid (16, 28), 256 threads. f-chunk = 224 = 7 x 32.
// ---------------------------------------------------------------------------
__global__ __launch_bounds__(256) void k_proj(const float* __restrict__ inp,
                                              const float* __restrict__ Wt){
    __shared__ __half Ah[128][40];
    __shared__ __half Bh[32][40];
    const int t = threadIdx.x, wid = t >> 5, l = t & 31;
    const int lr = l & 15, lc = (l >> 4) << 3;
    const int row0 = blockIdx.x * 128;
    const int fb0  = blockIdx.y * 224;

    const int arR[4] = { (t+0)>>3, (t+256)>>3, (t+512)>>3, (t+768)>>3 };
    const int arC    = (t & 7)*4;
    const int wrR    = t >> 3, wrC = (t & 7)*4;

    float acc[4][4];
    #pragma unroll
    for (int i = 0; i < 4; i++)
        #pragma unroll
        for (int j = 0; j < 4; j++) acc[i][j] = 0.f;

    const uint32_t a_ah = s2u(Ah), a_bh = s2u(Bh);

    float4 xv[4], wv;
    #pragma unroll
    for (int i = 0; i < 4; i++)
        xv[i] = *(const float4*)(inp + (size_t)(row0 + arR[i])*NF + fb0 + arC);
    wv = *(const float4*)(Wt + (size_t)(fb0 + wrR)*NU + wrC);

    for (int s = 0; s < 7; s++){
        const int fb = fb0 + s*32;
        #pragma unroll
        for (int i = 0; i < 4; i++){
            uint2 h = cvt4h(xv[i]);
            *(uint2*)&Ah[arR[i]][arC] = h;
            *(uint2*)&g_xh[(size_t)(row0 + arR[i])*NF + fb + arC] = h;
        }
        *(uint2*)&Bh[wrR][wrC] = cvt4h(wv);
        __syncthreads();

        if (s < 6){
            const int fbn = fb0 + (s+1)*32;
            #pragma unroll
            for (int i = 0; i < 4; i++)
                xv[i] = *(const float4*)(inp + (size_t)(row0 + arR[i])*NF + fbn + arC);
            wv = *(const float4*)(Wt + (size_t)(fbn + wrR)*NU + wrC);
        }

        #pragma unroll
        for (int ks = 0; ks < 32; ks += 16){
            uint32_t fa[4];
            ldsm4(fa, a_ah + ((wid*16 + lr)*40 + ks + lc)*2);
            uint32_t fb4[8];
            ldsm4t(fb4 + 0, a_bh + ((ks + lr)*40 + 0  + lc)*2);
            ldsm4t(fb4 + 4, a_bh + ((ks + lr)*40 + 16 + lc)*2);
            #pragma unroll
            for (int ng = 0; ng < 4; ng++)
                mma_f16(acc[ng], fa, fb4[ng*2], fb4[ng*2+1]);
        }
        __syncthreads();
    }
    float* pp = g_pp + (size_t)blockIdx.y*NB*NL*NU;
    const int r0 = row0 + wid*16 + (l >> 2);
    const int c0 = (l & 3)*2;
    #pragma unroll
    for (int ng = 0; ng < 4; ng++){
        *(float2*)&pp[(size_t)r0*NU + ng*8 + c0]     = make_float2(acc[ng][0], acc[ng][1]);
        *(float2*)&pp[(size_t)(r0+8)*NU + ng*8 + c0] = make_float2(acc[ng][2], acc[ng][3]);
    }
}

// ---------------------------------------------------------------------------
// K_pred: reduce partials -> g_p
// ---------------------------------------------------------------------------
__global__ __launch_bounds__(256) void k_pred(){
    int i = blockIdx.x*256 + threadIdx.x;
    float s = 0.f;
    #pragma unroll
    for (int j = 0; j < KSPLIT; j++) s += g_pp[(size_t)j*NB*NL*NU + i];
    g_p[i] = s;
}

// ---------------------------------------------------------------------------
// K_attn: block handles (b, 8 queries). grid (32, 8), 256 threads (t = k).
// ---------------------------------------------------------------------------
__global__ __launch_bounds__(256) void k_attn(const float* __restrict__ bh,
                                              const float* __restrict__ Wa,
                                              const float* __restrict__ ba){
    __shared__ float ps[NL][33];
    __shared__ float pqb[8][32];
    __shared__ float was[32];
    __shared__ float red[8][8];
    __shared__ float inv[8];

    const int t = threadIdx.x;
    const int b = blockIdx.y;
    const int q0 = blockIdx.x * 8;
    const float* pb = g_p + b*NL*NU;
    const float ba0 = ba[0];

    #pragma unroll
    for (int i = 0; i < 32; i++){
        int idx = t + i*256;
        ps[idx >> 5][idx & 31] = pb[idx];
    }
    if (t < 32) was[t] = Wa[t];
    {
        int j = t >> 5, u = t & 31;
        pqb[j][u] = pb[(q0 + j)*NU + u] + bh[u];
    }
    __syncthreads();

    float e[8];
    #pragma unroll
    for (int j = 0; j < 8; j++){
        float acc = 0.f;
        #pragma unroll
        for (int u = 0; u < 32; u++)
            acc = fmaf(was[u], tanh_approx(pqb[j][u] + ps[t][u]), acc);
        float alpha = acc + ba0;
        float sg = 1.f / (1.f + __expf(-alpha));
        e[j] = __expf(sg);
    }

    #pragma unroll
    for (int j = 0; j < 8; j++){
        float w = e[j];
        #pragma unroll
        for (int o = 16; o > 0; o >>= 1) w += __shfl_xor_sync(0xffffffffu, w, o);
        if ((t & 31) == 0) red[t >> 5][j] = w;
    }
    __syncthreads();
    if (t < 8){
        float tot = 0.f;
        #pragma unroll
        for (int w = 0; w < 8; w++) tot += red[w][t];
        inv[t] = 1.f / tot;
    }
    __syncthreads();

    #pragma unroll
    for (int j = 0; j < 8; j++)
        g_af[(size_t)b*NL*NL + (size_t)(q0 + j)*NL + t] = __float2half(e[j] * inv[j]);
}

// ---------------------------------------------------------------------------
// K_out: out[b,q,f] = sum_k a[b,q,k]*x[b,k,f]   (single fp16 HMMA term)
// BM=128, BN=128, BK=64 (4 chunks); 8 warps 2(M)x4(N), warp tile 64x32.
// Pure cp.async.cg staging, 2-stage double buffer.
// grid (49, 2, 8), 256 threads, 2 CTA/SM.
// ---------------------------------------------------------------------------
// stage layout (bytes): Af 128*72*2 = 18432 | Bf 64*136*2 = 17408 -> 35840
#define STG    35840
#define OFF_B  18432
#define K3_SMEM (2*STG)

__global__ __launch_bounds__(256, 2) void k_out(float* __restrict__ out){
    extern __shared__ char sm[];
    const uint32_t smb = s2u(sm);
    const int t = threadIdx.x, wid = t >> 5, l = t & 31;
    const int lr = l & 15, lc = (l >> 4) << 3;
    const int b  = blockIdx.z;
    const int q0 = blockIdx.y * 128;
    const int f0 = blockIdx.x * 128;
    const int warp_m = wid >> 2, warp_n = wid & 3;   // 2 x 4

    const __half* gaf = g_af + ((size_t)b*NL + q0)*NL;
    const __half* gx  = g_xh + (size_t)b*NL*NF + f0;

    // A staging: 128 rows x 64 halves = 1024 x 16B -> 4 cp16/thread
    int aR[4];
    #pragma unroll
    for (int i = 0; i < 4; i++) aR[i] = (t + i*256) >> 3;   // 0..127
    const int aC = (t & 7)*8;                               // halves
    // B staging: 64 rows x 128 halves = 1024 x 16B -> 4 cp16/thread
    int bR[4];
    #pragma unroll
    for (int i = 0; i < 4; i++) bR[i] = (t + i*256) >> 4;   // 0..63
    const int bC = (t & 15)*8;                              // halves

    float acc[4][4][4];
    #pragma unroll
    for (int mt = 0; mt < 4; mt++)
        #pragma unroll
        for (int ng = 0; ng < 4; ng++)
            #pragma unroll
            for (int k = 0; k < 4; k++) acc[mt][ng][k] = 0.f;

    // ---- prologue: issue chunks 0 and 1 into stages 0,1
    #pragma unroll
    for (int c = 0; c < 2; c++){
        const uint32_t st = smb + c*STG;
        const int k0 = c*64;
        #pragma unroll
        for (int i = 0; i < 4; i++){
            cp16(st + (uint32_t)aR[i]*144 + aC*2,          gaf + (size_t)aR[i]*NL + k0 + aC);
            cp16(st + OFF_B + (uint32_t)bR[i]*272 + bC*2,  gx + (size_t)(k0 + bR[i])*NF + bC);
        }
        cp_commit();
    }

    for (int c = 0; c < 4; c++){
        cp_wait1();           // stage c ready (chunk c+1 may be in flight)
        __syncthreads();

        const uint32_t base = smb + (c & 1)*STG;
        #pragma unroll
        for (int ks = 0; ks < 64; ks += 16){
            uint32_t fb4[8];
            ldsm4t(fb4 + 0, base + OFF_B + ((ks + lr)*136 + warp_n*32 + 0  + lc)*2);
            ldsm4t(fb4 + 4, base + OFF_B + ((ks + lr)*136 + warp_n*32 + 16 + lc)*2);
            #pragma unroll
            for (int mt = 0; mt < 4; mt++){
                uint32_t fa[4];
                ldsm4(fa, base + ((warp_m*64 + mt*16 + lr)*144/2 + ks + lc)*2);
                #pragma unroll
                for (int ng = 0; ng < 4; ng++)
                    mma_f16(acc[mt][ng], fa, fb4[ng*2], fb4[ng*2+1]);
            }
        }
        __syncthreads();      // all warps done with this buffer

        if (c + 2 < 4){
            const int k0 = (c+2)*64;
            #pragma unroll
            for (int i = 0; i < 4; i++){
                cp16(base + (uint32_t)aR[i]*144 + aC*2,         gaf + (size_t)aR[i]*NL + k0 + aC);
                cp16(base + OFF_B + (uint32_t)bR[i]*272 + bC*2, gx + (size_t)(k0 + bR[i])*NF + bC);
            }
        }
        cp_commit();
    }

    // epilogue
    const int c0 = (l & 3)*2;
    #pragma unroll
    for (int mt = 0; mt < 4; mt++){
        const int row = q0 + warp_m*64 + mt*16 + (l >> 2);
        #pragma unroll
        for (int ng = 0; ng < 4; ng++){
            const int col = f0 + warp_n*32 + ng*8 + c0;
            *(float2*)&out[((size_t)(b*NL + row))*NF + col] =
                make_float2(acc[mt][ng][0], acc[mt][ng][1]);
            *(float2*)&out[((size_t)(b*NL + row + 8))*NF + col] =
                make_float2(acc[mt][ng][2], acc[mt][ng][3]);
        }
    }
}

// ---------------------------------------------------------------------------
extern "C" void kernel_launch(void* const* d_in, const int* in_sizes, int n_in,
                              void* d_out, int out_size){
    const float* inp = (const float*)d_in[0];
    const float* Wt  = (const float*)d_in[1];
    const float* bh  = (const float*)d_in[2];
    const float* Wa  = (const float*)d_in[3];
    const float* ba  = (const float*)d_in[4];
    float* out = (float*)d_out;

    static bool attr_set = false;
    if (!attr_set){
        cudaFuncSetAttribute(k_out, cudaFuncAttributeMaxDynamicSharedMemorySize, K3_SMEM);
        attr_set = true;
    }

    k_proj<<<dim3(16, KSPLIT), 256>>>(inp, Wt);
    k_pred<<<NB*NL*NU/256, 256>>>();
    k_attn<<<dim3(NL/8, NB), 256>>>(bh, Wa, ba);
    k_out<<<dim3(NF/128, NL/128, NB), 256, K3_SMEM>>>(out);
}

// round 10
// speedup vs baseline: 1.1032x; 1.0053x over previous
#include <cuda_runtime.h>
#include <cuda_fp16.h>
#include <cstdint>

#define NB 8
#define NL 256
#define NF 6272
#define NU 32
#define KSPLIT 28

// Scratch (no cudaMalloc allowed)
__device__ float g_p[NB*NL*NU];                      // projections (atomic-accumulated)
__device__ __half g_af[NB*NL*NL];                    // a (softmax) fp16 [b][q][k]
__device__ __half g_xh[(size_t)NB*NL*NF];            // inputs fp16 [b][k][f] (written by k_proj)

// ---------------------------------------------------------------------------
// helpers
// ---------------------------------------------------------------------------
__device__ __forceinline__ uint32_t s2u(const void* p){
    uint32_t a;
    asm("{ .reg .u64 t; cvta.to.shared.u64 t, %1; cvt.u32.u64 %0, t; }" : "=r"(a) : "l"(p));
    return a;
}
__device__ __forceinline__ float tanh_approx(float x){
    float y; asm("tanh.approx.f32 %0, %1;" : "=f"(y) : "f"(x)); return y;
}
__device__ __forceinline__ void ldsm4(uint32_t r[4], uint32_t a){
    asm volatile("ldmatrix.sync.aligned.m8n8.x4.shared.b16 {%0,%1,%2,%3}, [%4];"
                 : "=r"(r[0]), "=r"(r[1]), "=r"(r[2]), "=r"(r[3]) : "r"(a));
}
__device__ __forceinline__ void ldsm4t(uint32_t r[4], uint32_t a){
    asm volatile("ldmatrix.sync.aligned.m8n8.x4.trans.shared.b16 {%0,%1,%2,%3}, [%4];"
                 : "=r"(r[0]), "=r"(r[1]), "=r"(r[2]), "=r"(r[3]) : "r"(a));
}
__device__ __forceinline__ void mma_f16(float c[4], const uint32_t a[4], uint32_t b0, uint32_t b1){
    asm volatile(
        "mma.sync.aligned.m16n8k16.row.col.f32.f16.f16.f32 "
        "{%0,%1,%2,%3}, {%4,%5,%6,%7}, {%8,%9}, {%0,%1,%2,%3};"
        : "+f"(c[0]), "+f"(c[1]), "+f"(c[2]), "+f"(c[3])
        : "r"(a[0]), "r"(a[1]), "r"(a[2]), "r"(a[3]), "r"(b0), "r"(b1));
}
__device__ __forceinline__ uint2 cvt4h(float4 v){
    __half h[4];
    h[0] = __float2half(v.x); h[1] = __float2half(v.y);
    h[2] = __float2half(v.z); h[3] = __float2half(v.w);
    return *(uint2*)h;
}
__device__ __forceinline__ void cp16(uint32_t dst, const void* src){
    asm volatile("cp.async.cg.shared.global [%0], [%1], 16;" :: "r"(dst), "l"(src));
}
__device__ __forceinline__ void cp_commit(){ asm volatile("cp.async.commit_group;"); }
__device__ __forceinline__ void cp_wait0(){ asm volatile("cp.async.wait_group 0;"); }

// ---------------------------------------------------------------------------
// K_proj: g_p += x[rows, fchunk] @ Wt[fchunk, 32]  (fp16 HMMA, atomic partials)
// Also writes g_xh (inputs as fp16). grid (16, 28), 256 threads.
// ---------------------------------------------------------------------------
__global__ __launch_bounds__(256) void k_proj(const float* __restrict__ inp,
                                              const float* __restrict__ Wt){
    __shared__ __half Ah[128][40];
    __shared__ __half Bh[32][40];
    const int t = threadIdx.x, wid = t >> 5, l = t & 31;
    const int lr = l & 15, lc = (l >> 4) << 3;
    const int row0 = blockIdx.x * 128;
    const int fb0  = blockIdx.y * 224;

    const int arR[4] = { (t+0)>>3, (t+256)>>3, (t+512)>>3, (t+768)>>3 };
    const int arC    = (t & 7)*4;
    const int wrR    = t >> 3, wrC = (t & 7)*4;

    float acc[4][4];
    #pragma unroll
    for (int i = 0; i < 4; i++)
        #pragma unroll
        for (int j = 0; j < 4; j++) acc[i][j] = 0.f;

    const uint32_t a_ah = s2u(Ah), a_bh = s2u(Bh);

    float4 xv[4], wv;
    #pragma unroll
    for (int i = 0; i < 4; i++)
        xv[i] = *(const float4*)(inp + (size_t)(row0 + arR[i])*NF + fb0 + arC);
    wv = *(const float4*)(Wt + (size_t)(fb0 + wrR)*NU + wrC);

    for (int s = 0; s < 7; s++){
        const int fb = fb0 + s*32;
        #pragma unroll
        for (int i = 0; i < 4; i++){
            uint2 h = cvt4h(xv[i]);
            *(uint2*)&Ah[arR[i]][arC] = h;
            *(uint2*)&g_xh[(size_t)(row0 + arR[i])*NF + fb + arC] = h;
        }
        *(uint2*)&Bh[wrR][wrC] = cvt4h(wv);
        __syncthreads();

        if (s < 6){
            const int fbn = fb0 + (s+1)*32;
            #pragma unroll
            for (int i = 0; i < 4; i++)
                xv[i] = *(const float4*)(inp + (size_t)(row0 + arR[i])*NF + fbn + arC);
            wv = *(const float4*)(Wt + (size_t)(fbn + wrR)*NU + wrC);
        }

        #pragma unroll
        for (int ks = 0; ks < 32; ks += 16){
            uint32_t fa[4];
            ldsm4(fa, a_ah + ((wid*16 + lr)*40 + ks + lc)*2);
            uint32_t fb4[8];
            ldsm4t(fb4 + 0, a_bh + ((ks + lr)*40 + 0  + lc)*2);
            ldsm4t(fb4 + 4, a_bh + ((ks + lr)*40 + 16 + lc)*2);
            #pragma unroll
            for (int ng = 0; ng < 4; ng++)
                mma_f16(acc[ng], fa, fb4[ng*2], fb4[ng*2+1]);
        }
        __syncthreads();
    }
    const int r0 = row0 + wid*16 + (l >> 2);
    const int c0 = (l & 3)*2;
    #pragma unroll
    for (int ng = 0; ng < 4; ng++){
        atomicAdd(&g_p[(size_t)r0*NU + ng*8 + c0],     acc[ng][0]);
        atomicAdd(&g_p[(size_t)r0*NU + ng*8 + c0 + 1], acc[ng][1]);
        atomicAdd(&g_p[(size_t)(r0+8)*NU + ng*8 + c0],     acc[ng][2]);
        atomicAdd(&g_p[(size_t)(r0+8)*NU + ng*8 + c0 + 1], acc[ng][3]);
    }
}

// ---------------------------------------------------------------------------
// K_attn: block handles (b, 8 queries). grid (32, 8), 256 threads (t = k).
// ---------------------------------------------------------------------------
__global__ __launch_bounds__(256) void k_attn(const float* __restrict__ bh,
                                              const float* __restrict__ Wa,
                                              const float* __restrict__ ba){
    __shared__ float ps[NL][33];
    __shared__ float pqb[8][32];
    __shared__ float was[32];
    __shared__ float red[8][8];
    __shared__ float inv[8];

    const int t = threadIdx.x;
    const int b = blockIdx.y;
    const int q0 = blockIdx.x * 8;
    const float* pb = g_p + b*NL*NU;
    const float ba0 = ba[0];

    #pragma unroll
    for (int i = 0; i < 32; i++){
        int idx = t + i*256;
        ps[idx >> 5][idx & 31] = pb[idx];
    }
    if (t < 32) was[t] = Wa[t];
    {
        int j = t >> 5, u = t & 31;
        pqb[j][u] = pb[(q0 + j)*NU + u] + bh[u];
    }
    __syncthreads();

    float e[8];
    #pragma unroll
    for (int j = 0; j < 8; j++){
        float acc = 0.f;
        #pragma unroll
        for (int u = 0; u < 32; u++)
            acc = fmaf(was[u], tanh_approx(pqb[j][u] + ps[t][u]), acc);
        float alpha = acc + ba0;
        float sg = 1.f / (1.f + __expf(-alpha));
        e[j] = __expf(sg);
    }

    #pragma unroll
    for (int j = 0; j < 8; j++){
        float w = e[j];
        #pragma unroll
        for (int o = 16; o > 0; o >>= 1) w += __shfl_xor_sync(0xffffffffu, w, o);
        if ((t & 31) == 0) red[t >> 5][j] = w;
    }
    __syncthreads();
    if (t < 8){
        float tot = 0.f;
        #pragma unroll
        for (int w = 0; w < 8; w++) tot += red[w][t];
        inv[t] = 1.f / tot;
    }
    __syncthreads();

    #pragma unroll
    for (int j = 0; j < 8; j++)
        g_af[(size_t)b*NL*NL + (size_t)(q0 + j)*NL + t] = __float2half(e[j] * inv[j]);
}

// ---------------------------------------------------------------------------
// K_out: out[b,q,f] = sum_k a[b,q,k]*x[b,k,f]   (single fp16 HMMA term)
// BM=128, BN=128, BK=64 (4 chunks); 4 warps 2(M)x2(N), warp tile 64x64.
// 3-stage cp.async.cg ring; fragment double-buffering across ks-steps AND
// chunk boundaries (stage c+1 proven complete under wait_group 0 at chunk c).
// grid (49, 2, 8), 128 threads, 2 CTA/SM.
// ---------------------------------------------------------------------------
// stage layout (bytes): Af 128*72*2 = 18432 | Bf 64*136*2 = 17408 -> 35840
#define STG    35840
#define OFF_B  18432
#define K3_SMEM (3*STG)

__global__ __launch_bounds__(128, 2) void k_out(float* __restrict__ out){
    extern __shared__ char sm[];
    const uint32_t smb = s2u(sm);
    const int t = threadIdx.x, wid = t >> 5, l = t & 31;
    const int lr = l & 15, lc = (l >> 4) << 3;
    const int b  = blockIdx.z;
    const int q0 = blockIdx.y * 128;
    const int f0 = blockIdx.x * 128;
    const int warp_m = wid >> 1, warp_n = wid & 1;   // 2 x 2

    const __half* gaf = g_af + ((size_t)b*NL + q0)*NL;
    const __half* gx  = g_xh + (size_t)b*NL*NF + f0;

    // A staging: 128 rows x 64 halves = 1024 x 16B -> 8 cp16/thread
    int aR[8];
    #pragma unroll
    for (int i = 0; i < 8; i++) aR[i] = (t + i*128) >> 3;   // 0..127
    const int aC = (t & 7)*8;                               // halves
    // B staging: 64 rows x 128 halves = 1024 x 16B -> 8 cp16/thread
    int bR[8];
    #pragma unroll
    for (int i = 0; i < 8; i++) bR[i] = (t + i*128) >> 4;   // 0..63
    const int bC = (t & 15)*8;                              // halves

    float acc[4][8][4];
    #pragma unroll
    for (int mt = 0; mt < 4; mt++)
        #pragma unroll
        for (int ng = 0; ng < 8; ng++)
            #pragma unroll
            for (int k = 0; k < 4; k++) acc[mt][ng][k] = 0.f;

    uint32_t fa[2][4][4], fb[2][16];

    // ---- prologue: issue chunks 0 and 1 into stages 0,1
    #pragma unroll
    for (int c = 0; c < 2; c++){
        const uint32_t st = smb + c*STG;
        const int k0 = c*64;
        #pragma unroll
        for (int i = 0; i < 8; i++){
            cp16(st + (uint32_t)aR[i]*144 + aC*2,          gaf + (size_t)aR[i]*NL + k0 + aC);
            cp16(st + OFF_B + (uint32_t)bR[i]*272 + bC*2,  gx + (size_t)(k0 + bR[i])*NF + bC);
        }
        cp_commit();
    }

    #define LOAD_FRAGS(buf, base, ks)                                                   \
        do {                                                                             \
            _Pragma("unroll")                                                            \
            for (int mt = 0; mt < 4; mt++)                                               \
                ldsm4(fa[buf][mt], (base) + ((warp_m*64 + mt*16 + lr)*72 + (ks) + lc)*2);\
            _Pragma("unroll")                                                            \
            for (int g = 0; g < 4; g++)                                                  \
                ldsm4t(fb[buf] + g*4, (base) + OFF_B + (((ks) + lr)*136 + warp_n*64 + g*16 + lc)*2); \
        } while(0)

    for (int c = 0; c < 4; c++){
        cp_wait0();            // all issued stages (incl. c+1) complete
        __syncthreads();       // ...and visible; also orders prior reads before next cp

        if (c < 2){
            const uint32_t st = smb + ((c+2)%3)*STG;
            const int k0 = (c+2)*64;
            #pragma unroll
            for (int i = 0; i < 8; i++){
                cp16(st + (uint32_t)aR[i]*144 + aC*2,         gaf + (size_t)aR[i]*NL + k0 + aC);
                cp16(st + OFF_B + (uint32_t)bR[i]*272 + bC*2, gx + (size_t)(k0 + bR[i])*NF + bC);
            }
            cp_commit();
        }

        const uint32_t base = smb + (c % 3)*STG;
        const uint32_t nbase = smb + ((c+1) % 3)*STG;
        if (c == 0) LOAD_FRAGS(0, base, 0);

        #pragma unroll
        for (int ks2 = 0; ks2 < 4; ks2++){
            const int mb = ks2 & 1, lb = mb ^ 1;
            if (ks2 < 3)      LOAD_FRAGS(lb, base, (ks2+1)*16);
            else if (c < 3)   LOAD_FRAGS(lb, nbase, 0);
            #pragma unroll
            for (int mt = 0; mt < 4; mt++)
                #pragma unroll
                for (int ng = 0; ng < 8; ng++)
                    mma_f16(acc[mt][ng], fa[mb][mt], fb[mb][ng*2], fb[mb][ng*2+1]);
        }
    }

    // epilogue
    const int c0 = (l & 3)*2;
    #pragma unroll
    for (int mt = 0; mt < 4; mt++){
        const int row = q0 + warp_m*64 + mt*16 + (l >> 2);
        #pragma unroll
        for (int ng = 0; ng < 8; ng++){
            const int col = f0 + warp_n*64 + ng*8 + c0;
            *(float2*)&out[((size_t)(b*NL + row))*NF + col] =
                make_float2(acc[mt][ng][0], acc[mt][ng][1]);
            *(float2*)&out[((size_t)(b*NL + row + 8))*NF + col] =
                make_float2(acc[mt][ng][2], acc[mt][ng][3]);
        }
    }
}

// ---------------------------------------------------------------------------
extern "C" void kernel_launch(void* const* d_in, const int* in_sizes, int n_in,
                              void* d_out, int out_size){
    const float* inp = (const float*)d_in[0];
    const float* Wt  = (const float*)d_in[1];
    const float* bh  = (const float*)d_in[2];
    const float* Wa  = (const float*)d_in[3];
    const float* ba  = (const float*)d_in[4];
    float* out = (float*)d_out;

    static bool attr_set = false;
    if (!attr_set){
        cudaFuncSetAttribute(k_out, cudaFuncAttributeMaxDynamicSharedMemorySize, K3_SMEM);
        attr_set = true;
    }

    void* gp_addr = nullptr;
    cudaGetSymbolAddress(&gp_addr, g_p);
    cudaMemsetAsync(gp_addr, 0, sizeof(float)*NB*NL*NU);

    k_proj<<<dim3(16, KSPLIT), 256>>>(inp, Wt);
    k_attn<<<dim3(NL/8, NB), 256>>>(bh, Wa, ba);
    k_out<<<dim3(NF/128, NL/128, NB), 128, K3_SMEM>>>(out);
}